// round 14
// baseline (speedup 1.0000x reference)
#include <cuda_runtime.h>
#include <cuda_fp16.h>
#include <cstdint>
#include <math.h>

typedef unsigned long long ull;

// ---------------- problem dims ----------------
#define NE     16384
#define CD     256
#define HW     1024
#define NTOK   4096
#define ZQ_N   (NTOK * CD)
#define NCUTS  32
#define EMB    512
#define BATCH  4

// ---------------- GEMM tiling ----------------
// Persistent: 296 CTAs (2/SM x 148). Work = 2048 tiles of 128 tokens x 256 codes,
// contiguous static ranges ordered (mtile, ngrp) so A (64KB, XOR-swizzled) stays
// resident across a run. B streamed as 128-code x 64-k slices (16KB), 3-stage
// cp.async pipeline rolling across tile boundaries. fp16 HMMA, f16 acc.
#define APLANE  65536
#define BTILE   16384
#define SMEM_B  (APLANE + 3 * BTILE)   // 114688
#define NTILES  2048                   // 32 mtiles x 64 ngrps
#define NWORK   296

// ---------------- device globals ----------------
__device__ __align__(16) __half g_Ah[NTOK * CD];
__device__ __align__(16) __half g_Bh[NE * CD];
__device__ __align__(16) float g_zt[NTOK * CD];      // fp32 z, token-major (for fixup)
__device__ float g_hn[NE];
__device__ ull   g_top[(size_t)NTOK * 256];          // 4 keys per (token, 256-code granule)

// ---------------- asm helpers ----------------
static __device__ __forceinline__ uint32_t smem_u32(const void* p) {
    uint32_t a;
    asm("{ .reg .u64 t; cvta.to.shared.u64 t, %1; cvt.u32.u64 %0, t; }" : "=r"(a) : "l"(p));
    return a;
}
static __device__ __forceinline__ void cp16(uint32_t dst, const void* src) {
    asm volatile("cp.async.cg.shared.global [%0], [%1], 16;" :: "r"(dst), "l"(src));
}
static __device__ __forceinline__ void cp_commit() {
    asm volatile("cp.async.commit_group;");
}
template <int N> static __device__ __forceinline__ void cp_wait() {
    asm volatile("cp.async.wait_group %0;" :: "n"(N));
}
#define LDSM4(r, addr) \
    asm volatile("ldmatrix.sync.aligned.m8n8.x4.shared.b16 {%0,%1,%2,%3}, [%4];" \
        : "=r"((r)[0]), "=r"((r)[1]), "=r"((r)[2]), "=r"((r)[3]) : "r"(addr))
#define MMAF16(d, a, b0, b1) \
    asm volatile("mma.sync.aligned.m16n8k16.row.col.f16.f16.f16.f16 " \
        "{%0,%1},{%2,%3,%4,%5},{%6,%7},{%0,%1};" \
        : "+r"((d)[0]), "+r"((d)[1]) \
        : "r"((a)[0]), "r"((a)[1]), "r"((a)[2]), "r"((a)[3]), "r"(b0), "r"(b1))

static __device__ __forceinline__ uint32_t mono_f32(float f) {
    uint32_t b = __float_as_uint(f);
    return b ^ ((uint32_t)(((int)b) >> 31) | 0x80000000u);
}
static __device__ __forceinline__ ull umax64(ull a, ull b) { return a > b ? a : b; }
static __device__ __forceinline__ ull pack_key(float s, int n) {
    return ((ull)mono_f32(s) << 32) | (ull)(NE - 1 - n);
}

// ================= prep: fused z/codebook -> f16 (+ fp32 zt, half-norms) =================
#define A_BLKS (NTOK * 32 / 8 / 32)    // 512 blocks (4096 warps)
#define B_BLKS ((NE * 32) / 256)       // 2048
__global__ void convAB_kernel(const float* __restrict__ z, const float* __restrict__ cb) {
    if (blockIdx.x < A_BLKS) {
        const int gw = blockIdx.x * 8 + (threadIdx.x >> 5);
        const int lane = threadIdx.x & 31;
        const int tg = gw >> 5, c8 = gw & 31;
        const int token = tg * 32 + lane;
        const int bb = token >> 10, p = token & 1023;
        __align__(16) __half h[8];
        __align__(16) float v[8];
        #pragma unroll
        for (int i = 0; i < 8; i++) {
            v[i] = z[((size_t)bb * CD + c8 * 8 + i) * HW + p];   // coalesced over lane
            h[i] = __float2half(v[i]);
        }
        *(uint4*)&g_Ah[(size_t)token * CD + c8 * 8] = *(const uint4*)h;
        *(float4*)&g_zt[(size_t)token * CD + c8 * 8]     = *(const float4*)v;
        *(float4*)&g_zt[(size_t)token * CD + c8 * 8 + 4] = *(const float4*)(v + 4);
        return;
    }
    int t = (blockIdx.x - A_BLKS) * 256 + threadIdx.x;
    int n = t >> 5, c8 = t & 31;
    __align__(16) __half h[8];
    float s = 0.f;
    #pragma unroll
    for (int i = 0; i < 8; i++) {
        float v = cb[(size_t)n * CD + c8 * 8 + i];
        h[i] = __float2half(v);
        s = fmaf(v, v, s);
    }
    *(uint4*)&g_Bh[(size_t)n * CD + c8 * 8] = *(const uint4*)h;
    #pragma unroll
    for (int o = 16; o; o >>= 1) s += __shfl_xor_sync(0xffffffffu, s, o);
    if ((t & 31) == 0) g_hn[n] = 0.5f * s;
}

// ================= persistent tensor-core VQ GEMM (nomination pass) =================
__global__ void __launch_bounds__(256, 2) vq_gemm() {
    extern __shared__ unsigned char smem[];
    const uint32_t sb = smem_u32(smem);
    const int tid = threadIdx.x;
    const int lane = tid & 31;
    const int wid = tid >> 5;
    const int wm = wid >> 1, wn = wid & 1;   // 4 x 2 warps, each 32m x 64n

    const int w = blockIdx.x;
    const int t0 = (w * NTILES) / NWORK;
    const int t1 = ((w + 1) * NTILES) / NWORK;

    const int arow = tid >> 1, ahalf = tid & 1;
    const int brow = tid >> 1, bhalf = tid & 1;
    const uint32_t a_sm_row = sb + arow * 512;
    const int ar7l = arow & 7;
    const int br7l = brow & 7;

    const int chi = lane >> 4;
    uint32_t a_row_sm[2]; int ar7[2];
    #pragma unroll
    for (int mi = 0; mi < 2; mi++) {
        const int rowA = wm * 32 + mi * 16 + (lane & 15);
        a_row_sm[mi] = sb + rowA * 512;
        ar7[mi] = rowA & 7;
    }
    uint32_t b_row_off[4]; int br7[4];
    #pragma unroll
    for (int nf = 0; nf < 4; nf++) {
        const int rowB = wn * 64 + nf * 16 + (lane & 15);
        b_row_off[nf] = rowB * 128;
        br7[nf] = rowB & 7;
    }
    const int cc = (lane & 3) * 2;

    uint32_t acc[2][8][2];
    #pragma unroll
    for (int mi = 0; mi < 2; mi++)
        #pragma unroll
        for (int ni = 0; ni < 8; ni++) { acc[mi][ni][0] = 0u; acc[mi][ni][1] = 0u; }

    float s1[2][2], s2[2][2];
    int   i1[2][2], i2[2][2];
    #pragma unroll
    for (int mi = 0; mi < 2; mi++)
        #pragma unroll
        for (int h = 0; h < 2; h++) {
            s1[mi][h] = -INFINITY; s2[mi][h] = -INFINITY;
            i1[mi][h] = 0;         i2[mi][h] = 0;
        }

    int T = t0;
    while (T < t1) {
        const int mtile = T >> 6;
        const int segEnd = min(t1, (mtile + 1) << 6);
        const int nsl = (segEnd - T) * 8;

        {
            const char* Abase = (const char*)(g_Ah + (size_t)mtile * 128 * CD);
            const char* asrc = Abase + (size_t)arow * 512 + ahalf * 256;
            #pragma unroll
            for (int j = 0; j < 16; j++) {
                const int c16 = ahalf * 16 + j;
                const uint32_t dst = a_sm_row + (c16 >> 3) * 128 + (((c16 & 7) ^ ar7l) << 4);
                cp16(dst, asrc + j * 16);
            }
            #pragma unroll
            for (int s = 0; s < 2; s++) {
                const int ngrp2 = T & 63;
                const int nt = s >> 2, ks = s & 3;
                const char* bsrc = (const char*)g_Bh
                    + (size_t)(ngrp2 * 256 + nt * 128 + brow) * 512 + ks * 128 + bhalf * 64;
                const uint32_t bdst = sb + APLANE + s * BTILE + brow * 128;
                #pragma unroll
                for (int j = 0; j < 4; j++) {
                    const int c16 = bhalf * 4 + j;
                    cp16(bdst + ((c16 ^ br7l) << 4), bsrc + j * 16);
                }
                cp_commit();
            }
        }

        int stage = 0;
        for (int si = 0; si < nsl; si++) {
            const int tile = T + (si >> 3);
            const int s = si & 7, nt = (s >> 2) & 1, ks = s & 3;

            cp_wait<1>();
            __syncthreads();

            const int nsi = si + 2;
            if (nsi < nsl) {
                int pst = stage + 2; if (pst >= 3) pst -= 3;
                const int ntile2 = T + (nsi >> 3);
                const int s2v = nsi & 7, nnt = (s2v >> 2) & 1, nks = s2v & 3;
                const int ngrp2 = ntile2 & 63;
                const char* bsrc = (const char*)g_Bh
                    + (size_t)(ngrp2 * 256 + nnt * 128 + brow) * 512 + nks * 128 + bhalf * 64;
                const uint32_t bdst = sb + APLANE + pst * BTILE + brow * 128;
                #pragma unroll
                for (int j = 0; j < 4; j++) {
                    const int c16 = bhalf * 4 + j;
                    cp16(bdst + ((c16 ^ br7l) << 4), bsrc + j * 16);
                }
            }
            cp_commit();

            const uint32_t sbB = sb + APLANE + stage * BTILE;
            #pragma unroll
            for (int kk = 0; kk < 4; kk++) {
                uint32_t a[2][4], b[4][4];
                const int c16a = kk * 2 + chi;
                #pragma unroll
                for (int mi = 0; mi < 2; mi++)
                    LDSM4(a[mi], a_row_sm[mi] + ks * 128 + ((c16a ^ ar7[mi]) << 4));
                #pragma unroll
                for (int nf = 0; nf < 4; nf++)
                    LDSM4(b[nf], sbB + b_row_off[nf] + ((c16a ^ br7[nf]) << 4));
                #pragma unroll
                for (int mi = 0; mi < 2; mi++)
                    #pragma unroll
                    for (int nf = 0; nf < 4; nf++) {
                        MMAF16(acc[mi][nf * 2 + 0], a[mi], b[nf][0], b[nf][2]);
                        MMAF16(acc[mi][nf * 2 + 1], a[mi], b[nf][1], b[nf][3]);
                    }
            }
            if (++stage == 3) stage = 0;

            if (ks == 3) {
                const int nbase = (tile & 63) * 256 + nt * 128 + wn * 64;
                #pragma unroll
                for (int ni = 0; ni < 8; ni++) {
                    const int n0 = nbase + ni * 8 + cc;
                    const float hn0 = __ldg(&g_hn[n0]);
                    const float hn1 = __ldg(&g_hn[n0 + 1]);
                    #pragma unroll
                    for (int mi = 0; mi < 2; mi++)
                        #pragma unroll
                        for (int h = 0; h < 2; h++) {
                            const float2 f = __half22float2(*(__half2*)&acc[mi][ni][h]);
                            const float sc0 = f.x - hn0;
                            const float sc1 = f.y - hn1;
                            if (sc0 > s1[mi][h]) {
                                s2[mi][h] = s1[mi][h]; i2[mi][h] = i1[mi][h];
                                s1[mi][h] = sc0;       i1[mi][h] = n0;
                            } else if (sc0 > s2[mi][h]) {
                                s2[mi][h] = sc0; i2[mi][h] = n0;
                            }
                            if (sc1 > s1[mi][h]) {
                                s2[mi][h] = s1[mi][h]; i2[mi][h] = i1[mi][h];
                                s1[mi][h] = sc1;       i1[mi][h] = n0 + 1;
                            } else if (sc1 > s2[mi][h]) {
                                s2[mi][h] = sc1; i2[mi][h] = n0 + 1;
                            }
                            acc[mi][ni][h] = 0u;
                        }
                }
            }

            if (s == 7) {
                #pragma unroll
                for (int mi = 0; mi < 2; mi++)
                    #pragma unroll
                    for (int h = 0; h < 2; h++) {
                        float a1 = s1[mi][h], a2 = s2[mi][h];
                        int   x1 = i1[mi][h], x2 = i2[mi][h];
                        #pragma unroll
                        for (int off = 1; off <= 2; off <<= 1) {
                            float b1 = __shfl_xor_sync(0xffffffffu, a1, off);
                            float b2 = __shfl_xor_sync(0xffffffffu, a2, off);
                            int   y1 = __shfl_xor_sync(0xffffffffu, x1, off);
                            int   y2 = __shfl_xor_sync(0xffffffffu, x2, off);
                            if (b1 > a1 || (b1 == a1 && y1 < x1)) {
                                float t = a1; a1 = b1; b1 = t;
                                int  ti = x1; x1 = y1; y1 = ti;
                                t = a2; a2 = b2; b2 = t;
                                ti = x2; x2 = y2; y2 = ti;
                            }
                            if (b1 > a2 || (b1 == a2 && y1 < x2)) { a2 = b1; x2 = y1; }
                        }
                        if ((lane & 3) == 0) {
                            const int token = mtile * 128 + wm * 32 + mi * 16 + h * 8 + (lane >> 2);
                            ull* dst = g_top + (size_t)token * 256 + (tile & 63) * 4 + wn * 2;
                            dst[0] = pack_key(a1, x1);
                            dst[1] = pack_key(a2, x2);
                        }
                        s1[mi][h] = -INFINITY; s2[mi][h] = -INFINITY;
                        i1[mi][h] = 0;         i2[mi][h] = 0;
                    }
            }
        }

        cp_wait<0>();
        __syncthreads();
        T = segEnd;
    }
}

// ================= fused fixup + gather z_q + spherical distance =================
#define GT_BLKS (NTOK / 32)         // 128
#define SPH_BLKS ((EMB * 8) / 256)  // 16
__global__ void finish_kernel(const float* __restrict__ cb, const float* __restrict__ ie,
                              const float* __restrict__ pr, float* __restrict__ out) {
    if (blockIdx.x < GT_BLKS) {
        extern __shared__ float ts[];              // [32 tokens][257]
        int* idx_sm = (int*)(ts + 32 * 257);       // [32] winning indices
        const int tid = threadIdx.x;
        const int wrp = tid >> 5, lane = tid & 31;
        const int t0 = blockIdx.x * 32;

        // ---- phase A: fixup (each warp: 4 tokens, top-4 extract + exact rescore) ----
        #pragma unroll
        for (int tt = 0; tt < 4; tt++) {
            const int token = t0 + wrp * 4 + tt;

            const ull* tp = g_top + (size_t)token * 256;
            ull k[8];
            #pragma unroll
            for (int i = 0; i < 8; i++) k[i] = tp[lane + 32 * i];

            int cand[4];
            #pragma unroll
            for (int r = 0; r < 4; r++) {
                ull m = 0;
                #pragma unroll
                for (int i = 0; i < 8; i++) m = umax64(m, k[i]);
                #pragma unroll
                for (int off = 16; off; off >>= 1)
                    m = umax64(m, __shfl_xor_sync(0xffffffffu, m, off));
                #pragma unroll
                for (int i = 0; i < 8; i++) if (k[i] == m) k[i] = 0;
                cand[r] = (NE - 1) - (int)(m & 0xFFFFFFFFull);
            }

            float zv[8];
            #pragma unroll
            for (int i = 0; i < 8; i++)
                zv[i] = g_zt[(size_t)token * CD + lane + 32 * i];

            ull bestk = 0;
            #pragma unroll
            for (int r = 0; r < 4; r++) {
                const int n = cand[r];
                const float* crow = cb + (size_t)n * CD;
                float s = 0.f;
                #pragma unroll
                for (int i = 0; i < 8; i++) s = fmaf(zv[i], __ldg(&crow[lane + 32 * i]), s);
                #pragma unroll
                for (int off = 16; off; off >>= 1) s += __shfl_xor_sync(0xffffffffu, s, off);
                s -= g_hn[n];
                bestk = umax64(bestk, pack_key(s, n));
            }
            if (lane == 0) idx_sm[wrp * 4 + tt] = (NE - 1) - (int)(bestk & 0xFFFFFFFFull);
        }
        __syncthreads();

        // ---- phase B: coalesced codebook row loads -> staged transpose ----
        const int r = tid >> 3, part = tid & 7;
        const int n = idx_sm[r];
        const float* crow = cb + (size_t)n * CD;
        float* dst = ts + r * 257;
        #pragma unroll
        for (int j = 0; j < 8; j++) {
            const int c = part * 4 + j * 32;
            float4 v = *(const float4*)(crow + c);
            dst[c + 0] = v.x; dst[c + 1] = v.y; dst[c + 2] = v.z; dst[c + 3] = v.w;
        }
        __syncthreads();

        // ---- phase C: coalesced stores to [B,C,H,W] ----
        const int bb = t0 >> 10, p0 = t0 & 1023;
        float* ob = out + (size_t)bb * CD * HW + p0;
        #pragma unroll
        for (int i = 0; i < 32; i++) {
            const int c = wrp + 8 * i;
            ob[(size_t)c * HW + lane] = ts[lane * 257 + c];
        }
        return;
    }
    // ---- spherical distance: 4096 threads = 512 e x 8 cut-groups of 4 ----
    const int idx = (blockIdx.x - GT_BLKS) * 256 + threadIdx.x;
    const int e = idx >> 3, jg = idx & 7;
    float pv[BATCH];
    float pn = 0.f;
    #pragma unroll
    for (int b = 0; b < BATCH; b++) { pv[b] = pr[b * EMB + e]; pn += pv[b] * pv[b]; }
    pn = fmaxf(sqrtf(pn), 1e-12f);
    #pragma unroll
    for (int b = 0; b < BATCH; b++) pv[b] /= pn;
    float acc = 0.f;
    #pragma unroll
    for (int jj = 0; jj < 4; jj++) {
        const int j = jg * 4 + jj;
        float q[BATCH];
        float qn = 0.f;
        #pragma unroll
        for (int b = 0; b < BATCH; b++) {
            q[b] = ie[(size_t)(j * BATCH + b) * EMB + e];
            qn += q[b] * q[b];
        }
        qn = fmaxf(sqrtf(qn), 1e-12f);
        float d2 = 0.f;
        #pragma unroll
        for (int b = 0; b < BATCH; b++) {
            float df = q[b] / qn - pv[b];
            d2 += df * df;
        }
        float h = fminf(0.5f * sqrtf(d2), 1.0f);
        float a = asinf(h);
        acc += 2.0f * a * a;
    }
    #pragma unroll
    for (int off = 1; off <= 4; off <<= 1)
        acc += __shfl_xor_sync(0xffffffffu, acc, off);
    if (jg == 0) out[ZQ_N + e] = acc * (1.0f / NCUTS);
}

#define GT_SMEM (32 * 257 * 4 + 32 * 4)

// ================= launch =================
extern "C" void kernel_launch(void* const* d_in, const int* in_sizes, int n_in,
                              void* d_out, int out_size) {
    const float* z  = (const float*)d_in[0];
    const float* cb = (const float*)d_in[1];
    const float* ie = (const float*)d_in[2];
    const float* pr = (const float*)d_in[3];
    float* out = (float*)d_out;

    cudaFuncSetAttribute(vq_gemm, cudaFuncAttributeMaxDynamicSharedMemorySize, SMEM_B);
    cudaFuncSetAttribute(finish_kernel, cudaFuncAttributeMaxDynamicSharedMemorySize, GT_SMEM);

    convAB_kernel<<<A_BLKS + B_BLKS, 256>>>(z, cb);
    vq_gemm<<<NWORK, 256, SMEM_B>>>();
    finish_kernel<<<GT_BLKS + SPH_BLKS, 256, GT_SMEM>>>(cb, ie, pr, out);
}

// round 15
// speedup vs baseline: 1.0493x; 1.0493x over previous
#include <cuda_runtime.h>
#include <cuda_fp16.h>
#include <cstdint>
#include <math.h>

typedef unsigned long long ull;

// ---------------- problem dims ----------------
#define NE     16384
#define CD     256
#define HW     1024
#define NTOK   4096
#define ZQ_N   (NTOK * CD)
#define NCUTS  32
#define EMB    512
#define BATCH  4

// ---------------- GEMM tiling ----------------
// Persistent: 296 CTAs (2/SM x 148). Work = 2048 tiles of 128 tokens x 256 codes,
// contiguous static ranges ordered (mtile, ngrp) so A (64KB, XOR-swizzled) stays
// resident across a run. B streamed as 128-code x 64-k slices (16KB), 3-stage
// cp.async pipeline rolling across tile boundaries. fp16 HMMA, f16 acc.
#define APLANE  65536
#define BTILE   16384
#define SMEM_B  (APLANE + 3 * BTILE)   // 114688
#define NTILES  2048                   // 32 mtiles x 64 ngrps
#define NWORK   296

// ---------------- device globals ----------------
__device__ __align__(16) __half g_Ah[NTOK * CD];
__device__ __align__(16) __half g_Bh[NE * CD];
__device__ __align__(16) float g_zt[NTOK * CD];      // fp32 z, token-major (for fixup)
__device__ float g_hn[NE];
__device__ ull   g_top[(size_t)NTOK * 256];          // 4 keys per (token, 256-code granule)
__device__ int   g_best[NTOK];

// ---------------- asm helpers ----------------
static __device__ __forceinline__ uint32_t smem_u32(const void* p) {
    uint32_t a;
    asm("{ .reg .u64 t; cvta.to.shared.u64 t, %1; cvt.u32.u64 %0, t; }" : "=r"(a) : "l"(p));
    return a;
}
static __device__ __forceinline__ void cp16(uint32_t dst, const void* src) {
    asm volatile("cp.async.cg.shared.global [%0], [%1], 16;" :: "r"(dst), "l"(src));
}
static __device__ __forceinline__ void cp_commit() {
    asm volatile("cp.async.commit_group;");
}
template <int N> static __device__ __forceinline__ void cp_wait() {
    asm volatile("cp.async.wait_group %0;" :: "n"(N));
}
#define LDSM4(r, addr) \
    asm volatile("ldmatrix.sync.aligned.m8n8.x4.shared.b16 {%0,%1,%2,%3}, [%4];" \
        : "=r"((r)[0]), "=r"((r)[1]), "=r"((r)[2]), "=r"((r)[3]) : "r"(addr))
#define MMAF16(d, a, b0, b1) \
    asm volatile("mma.sync.aligned.m16n8k16.row.col.f16.f16.f16.f16 " \
        "{%0,%1},{%2,%3,%4,%5},{%6,%7},{%0,%1};" \
        : "+r"((d)[0]), "+r"((d)[1]) \
        : "r"((a)[0]), "r"((a)[1]), "r"((a)[2]), "r"((a)[3]), "r"(b0), "r"(b1))

static __device__ __forceinline__ uint32_t mono_f32(float f) {
    uint32_t b = __float_as_uint(f);
    return b ^ ((uint32_t)(((int)b) >> 31) | 0x80000000u);
}
static __device__ __forceinline__ ull umax64(ull a, ull b) { return a > b ? a : b; }
static __device__ __forceinline__ ull pack_key(float s, int n) {
    return ((ull)mono_f32(s) << 32) | (ull)(NE - 1 - n);
}

// ================= prep: fused z/codebook -> f16 (+ fp32 zt, half-norms) =================
#define A_BLKS (NTOK * 32 / 8 / 32)    // 512 blocks (4096 warps)
#define B_BLKS ((NE * 32) / 256)       // 2048
__global__ void convAB_kernel(const float* __restrict__ z, const float* __restrict__ cb) {
    if (blockIdx.x < A_BLKS) {
        const int gw = blockIdx.x * 8 + (threadIdx.x >> 5);
        const int lane = threadIdx.x & 31;
        const int tg = gw >> 5, c8 = gw & 31;
        const int token = tg * 32 + lane;
        const int bb = token >> 10, p = token & 1023;
        __align__(16) __half h[8];
        __align__(16) float v[8];
        #pragma unroll
        for (int i = 0; i < 8; i++) {
            v[i] = z[((size_t)bb * CD + c8 * 8 + i) * HW + p];   // coalesced over lane
            h[i] = __float2half(v[i]);
        }
        *(uint4*)&g_Ah[(size_t)token * CD + c8 * 8] = *(const uint4*)h;
        *(float4*)&g_zt[(size_t)token * CD + c8 * 8]     = *(const float4*)v;
        *(float4*)&g_zt[(size_t)token * CD + c8 * 8 + 4] = *(const float4*)(v + 4);
        return;
    }
    int t = (blockIdx.x - A_BLKS) * 256 + threadIdx.x;
    int n = t >> 5, c8 = t & 31;
    __align__(16) __half h[8];
    // vectorized codebook read: 2 x float4 (32B contiguous per thread)
    const float4 v0 = *(const float4*)(cb + (size_t)n * CD + c8 * 8);
    const float4 v1 = *(const float4*)(cb + (size_t)n * CD + c8 * 8 + 4);
    float s = 0.f;
    {
        const float vv[8] = {v0.x, v0.y, v0.z, v0.w, v1.x, v1.y, v1.z, v1.w};
        #pragma unroll
        for (int i = 0; i < 8; i++) {
            h[i] = __float2half(vv[i]);
            s = fmaf(vv[i], vv[i], s);
        }
    }
    *(uint4*)&g_Bh[(size_t)n * CD + c8 * 8] = *(const uint4*)h;
    #pragma unroll
    for (int o = 16; o; o >>= 1) s += __shfl_xor_sync(0xffffffffu, s, o);
    if ((t & 31) == 0) g_hn[n] = 0.5f * s;
}

// ================= persistent tensor-core VQ GEMM (nomination pass) =================
__global__ void __launch_bounds__(256, 2) vq_gemm() {
    extern __shared__ unsigned char smem[];
    const uint32_t sb = smem_u32(smem);
    const int tid = threadIdx.x;
    const int lane = tid & 31;
    const int wid = tid >> 5;
    const int wm = wid >> 1, wn = wid & 1;   // 4 x 2 warps, each 32m x 64n

    const int w = blockIdx.x;
    const int t0 = (w * NTILES) / NWORK;
    const int t1 = ((w + 1) * NTILES) / NWORK;

    const int arow = tid >> 1, ahalf = tid & 1;
    const int brow = tid >> 1, bhalf = tid & 1;
    const uint32_t a_sm_row = sb + arow * 512;
    const int ar7l = arow & 7;
    const int br7l = brow & 7;

    const int chi = lane >> 4;
    uint32_t a_row_sm[2]; int ar7[2];
    #pragma unroll
    for (int mi = 0; mi < 2; mi++) {
        const int rowA = wm * 32 + mi * 16 + (lane & 15);
        a_row_sm[mi] = sb + rowA * 512;
        ar7[mi] = rowA & 7;
    }
    uint32_t b_row_off[4]; int br7[4];
    #pragma unroll
    for (int nf = 0; nf < 4; nf++) {
        const int rowB = wn * 64 + nf * 16 + (lane & 15);
        b_row_off[nf] = rowB * 128;
        br7[nf] = rowB & 7;
    }
    const int cc = (lane & 3) * 2;

    uint32_t acc[2][8][2];
    #pragma unroll
    for (int mi = 0; mi < 2; mi++)
        #pragma unroll
        for (int ni = 0; ni < 8; ni++) { acc[mi][ni][0] = 0u; acc[mi][ni][1] = 0u; }

    float s1[2][2], s2[2][2];
    int   i1[2][2], i2[2][2];
    #pragma unroll
    for (int mi = 0; mi < 2; mi++)
        #pragma unroll
        for (int h = 0; h < 2; h++) {
            s1[mi][h] = -INFINITY; s2[mi][h] = -INFINITY;
            i1[mi][h] = 0;         i2[mi][h] = 0;
        }

    int T = t0;
    while (T < t1) {
        const int mtile = T >> 6;
        const int segEnd = min(t1, (mtile + 1) << 6);
        const int nsl = (segEnd - T) * 8;

        {
            const char* Abase = (const char*)(g_Ah + (size_t)mtile * 128 * CD);
            const char* asrc = Abase + (size_t)arow * 512 + ahalf * 256;
            #pragma unroll
            for (int j = 0; j < 16; j++) {
                const int c16 = ahalf * 16 + j;
                const uint32_t dst = a_sm_row + (c16 >> 3) * 128 + (((c16 & 7) ^ ar7l) << 4);
                cp16(dst, asrc + j * 16);
            }
            #pragma unroll
            for (int s = 0; s < 2; s++) {
                const int ngrp2 = T & 63;
                const int nt = s >> 2, ks = s & 3;
                const char* bsrc = (const char*)g_Bh
                    + (size_t)(ngrp2 * 256 + nt * 128 + brow) * 512 + ks * 128 + bhalf * 64;
                const uint32_t bdst = sb + APLANE + s * BTILE + brow * 128;
                #pragma unroll
                for (int j = 0; j < 4; j++) {
                    const int c16 = bhalf * 4 + j;
                    cp16(bdst + ((c16 ^ br7l) << 4), bsrc + j * 16);
                }
                cp_commit();
            }
        }

        int stage = 0;
        for (int si = 0; si < nsl; si++) {
            const int tile = T + (si >> 3);
            const int s = si & 7, nt = (s >> 2) & 1, ks = s & 3;

            cp_wait<1>();
            __syncthreads();

            const int nsi = si + 2;
            if (nsi < nsl) {
                int pst = stage + 2; if (pst >= 3) pst -= 3;
                const int ntile2 = T + (nsi >> 3);
                const int s2v = nsi & 7, nnt = (s2v >> 2) & 1, nks = s2v & 3;
                const int ngrp2 = ntile2 & 63;
                const char* bsrc = (const char*)g_Bh
                    + (size_t)(ngrp2 * 256 + nnt * 128 + brow) * 512 + nks * 128 + bhalf * 64;
                const uint32_t bdst = sb + APLANE + pst * BTILE + brow * 128;
                #pragma unroll
                for (int j = 0; j < 4; j++) {
                    const int c16 = bhalf * 4 + j;
                    cp16(bdst + ((c16 ^ br7l) << 4), bsrc + j * 16);
                }
            }
            cp_commit();

            const uint32_t sbB = sb + APLANE + stage * BTILE;
            #pragma unroll
            for (int kk = 0; kk < 4; kk++) {
                uint32_t a[2][4], b[4][4];
                const int c16a = kk * 2 + chi;
                #pragma unroll
                for (int mi = 0; mi < 2; mi++)
                    LDSM4(a[mi], a_row_sm[mi] + ks * 128 + ((c16a ^ ar7[mi]) << 4));
                #pragma unroll
                for (int nf = 0; nf < 4; nf++)
                    LDSM4(b[nf], sbB + b_row_off[nf] + ((c16a ^ br7[nf]) << 4));
                #pragma unroll
                for (int mi = 0; mi < 2; mi++)
                    #pragma unroll
                    for (int nf = 0; nf < 4; nf++) {
                        MMAF16(acc[mi][nf * 2 + 0], a[mi], b[nf][0], b[nf][2]);
                        MMAF16(acc[mi][nf * 2 + 1], a[mi], b[nf][1], b[nf][3]);
                    }
            }
            if (++stage == 3) stage = 0;

            if (ks == 3) {
                const int nbase = (tile & 63) * 256 + nt * 128 + wn * 64;
                #pragma unroll
                for (int ni = 0; ni < 8; ni++) {
                    const int n0 = nbase + ni * 8 + cc;
                    const float hn0 = __ldg(&g_hn[n0]);
                    const float hn1 = __ldg(&g_hn[n0 + 1]);
                    #pragma unroll
                    for (int mi = 0; mi < 2; mi++)
                        #pragma unroll
                        for (int h = 0; h < 2; h++) {
                            const float2 f = __half22float2(*(__half2*)&acc[mi][ni][h]);
                            const float sc0 = f.x - hn0;
                            const float sc1 = f.y - hn1;
                            if (sc0 > s1[mi][h]) {
                                s2[mi][h] = s1[mi][h]; i2[mi][h] = i1[mi][h];
                                s1[mi][h] = sc0;       i1[mi][h] = n0;
                            } else if (sc0 > s2[mi][h]) {
                                s2[mi][h] = sc0; i2[mi][h] = n0;
                            }
                            if (sc1 > s1[mi][h]) {
                                s2[mi][h] = s1[mi][h]; i2[mi][h] = i1[mi][h];
                                s1[mi][h] = sc1;       i1[mi][h] = n0 + 1;
                            } else if (sc1 > s2[mi][h]) {
                                s2[mi][h] = sc1; i2[mi][h] = n0 + 1;
                            }
                            acc[mi][ni][h] = 0u;
                        }
                }
            }

            if (s == 7) {
                #pragma unroll
                for (int mi = 0; mi < 2; mi++)
                    #pragma unroll
                    for (int h = 0; h < 2; h++) {
                        float a1 = s1[mi][h], a2 = s2[mi][h];
                        int   x1 = i1[mi][h], x2 = i2[mi][h];
                        #pragma unroll
                        for (int off = 1; off <= 2; off <<= 1) {
                            float b1 = __shfl_xor_sync(0xffffffffu, a1, off);
                            float b2 = __shfl_xor_sync(0xffffffffu, a2, off);
                            int   y1 = __shfl_xor_sync(0xffffffffu, x1, off);
                            int   y2 = __shfl_xor_sync(0xffffffffu, x2, off);
                            if (b1 > a1 || (b1 == a1 && y1 < x1)) {
                                float t = a1; a1 = b1; b1 = t;
                                int  ti = x1; x1 = y1; y1 = ti;
                                t = a2; a2 = b2; b2 = t;
                                ti = x2; x2 = y2; y2 = ti;
                            }
                            if (b1 > a2 || (b1 == a2 && y1 < x2)) { a2 = b1; x2 = y1; }
                        }
                        if ((lane & 3) == 0) {
                            const int token = mtile * 128 + wm * 32 + mi * 16 + h * 8 + (lane >> 2);
                            ull* dst = g_top + (size_t)token * 256 + (tile & 63) * 4 + wn * 2;
                            dst[0] = pack_key(a1, x1);
                            dst[1] = pack_key(a2, x2);
                        }
                        s1[mi][h] = -INFINITY; s2[mi][h] = -INFINITY;
                        i1[mi][h] = 0;         i2[mi][h] = 0;
                    }
            }
        }

        cp_wait<0>();
        __syncthreads();
        T = segEnd;
    }
}

// ================= fixup: global top-4 + exact fp32 rescore =================
__global__ void fixup_kernel(const float* __restrict__ cb) {
    const int token = blockIdx.x * 8 + (threadIdx.x >> 5);
    const int lane = threadIdx.x & 31;

    const ull* tp = g_top + (size_t)token * 256;
    ull k[8];
    #pragma unroll
    for (int i = 0; i < 8; i++) k[i] = tp[lane + 32 * i];

    int cand[4];
    #pragma unroll
    for (int r = 0; r < 4; r++) {
        ull m = 0;
        #pragma unroll
        for (int i = 0; i < 8; i++) m = umax64(m, k[i]);
        #pragma unroll
        for (int off = 16; off; off >>= 1)
            m = umax64(m, __shfl_xor_sync(0xffffffffu, m, off));
        #pragma unroll
        for (int i = 0; i < 8; i++) if (k[i] == m) k[i] = 0;
        cand[r] = (NE - 1) - (int)(m & 0xFFFFFFFFull);
    }

    float zv[8];
    #pragma unroll
    for (int i = 0; i < 8; i++)
        zv[i] = g_zt[(size_t)token * CD + lane + 32 * i];

    ull bestk = 0;
    #pragma unroll
    for (int r = 0; r < 4; r++) {
        const int n = cand[r];
        const float* crow = cb + (size_t)n * CD;
        float s = 0.f;
        #pragma unroll
        for (int i = 0; i < 8; i++) s = fmaf(zv[i], __ldg(&crow[lane + 32 * i]), s);
        #pragma unroll
        for (int off = 16; off; off >>= 1) s += __shfl_xor_sync(0xffffffffu, s, off);
        s -= g_hn[n];
        bestk = umax64(bestk, pack_key(s, n));
    }
    if (lane == 0) g_best[token] = (NE - 1) - (int)(bestk & 0xFFFFFFFFull);
}

// ================= gather z_q (smem transpose) + spherical distance =================
#define GT_BLKS (NTOK / 32)         // 128
#define SPH_BLKS ((EMB * 8) / 256)  // 16
__global__ void gather_sph_kernel(const float* __restrict__ cb, const float* __restrict__ ie,
                                  const float* __restrict__ pr, float* __restrict__ out) {
    if (blockIdx.x < GT_BLKS) {
        extern __shared__ float ts[];       // [32 tokens][257]
        const int tid = threadIdx.x;
        const int r = tid >> 3, part = tid & 7;
        const int n = g_best[blockIdx.x * 32 + r];
        const float* crow = cb + (size_t)n * CD;
        float* dst = ts + r * 257;
        #pragma unroll
        for (int j = 0; j < 8; j++) {
            const int c = part * 4 + j * 32;
            float4 v = *(const float4*)(crow + c);
            dst[c + 0] = v.x; dst[c + 1] = v.y; dst[c + 2] = v.z; dst[c + 3] = v.w;
        }
        __syncthreads();
        const int w = tid >> 5, l = tid & 31;
        const int t0 = blockIdx.x * 32;
        const int bb = t0 >> 10, p0 = t0 & 1023;
        float* ob = out + (size_t)bb * CD * HW + p0;
        #pragma unroll
        for (int i = 0; i < 32; i++) {
            const int c = w + 8 * i;
            ob[(size_t)c * HW + l] = ts[l * 257 + c];
        }
        return;
    }
    const int idx = (blockIdx.x - GT_BLKS) * 256 + threadIdx.x;
    const int e = idx >> 3, jg = idx & 7;
    float pv[BATCH];
    float pn = 0.f;
    #pragma unroll
    for (int b = 0; b < BATCH; b++) { pv[b] = pr[b * EMB + e]; pn += pv[b] * pv[b]; }
    pn = fmaxf(sqrtf(pn), 1e-12f);
    #pragma unroll
    for (int b = 0; b < BATCH; b++) pv[b] /= pn;
    float acc = 0.f;
    #pragma unroll
    for (int jj = 0; jj < 4; jj++) {
        const int j = jg * 4 + jj;
        float q[BATCH];
        float qn = 0.f;
        #pragma unroll
        for (int b = 0; b < BATCH; b++) {
            q[b] = ie[(size_t)(j * BATCH + b) * EMB + e];
            qn += q[b] * q[b];
        }
        qn = fmaxf(sqrtf(qn), 1e-12f);
        float d2 = 0.f;
        #pragma unroll
        for (int b = 0; b < BATCH; b++) {
            float df = q[b] / qn - pv[b];
            d2 += df * df;
        }
        float h = fminf(0.5f * sqrtf(d2), 1.0f);
        float a = asinf(h);
        acc += 2.0f * a * a;
    }
    #pragma unroll
    for (int off = 1; off <= 4; off <<= 1)
        acc += __shfl_xor_sync(0xffffffffu, acc, off);
    if (jg == 0) out[ZQ_N + e] = acc * (1.0f / NCUTS);
}

#define GT_SMEM (32 * 257 * 4)

// ================= launch =================
extern "C" void kernel_launch(void* const* d_in, const int* in_sizes, int n_in,
                              void* d_out, int out_size) {
    const float* z  = (const float*)d_in[0];
    const float* cb = (const float*)d_in[1];
    const float* ie = (const float*)d_in[2];
    const float* pr = (const float*)d_in[3];
    float* out = (float*)d_out;

    cudaFuncSetAttribute(vq_gemm, cudaFuncAttributeMaxDynamicSharedMemorySize, SMEM_B);
    cudaFuncSetAttribute(gather_sph_kernel, cudaFuncAttributeMaxDynamicSharedMemorySize, GT_SMEM);

    convAB_kernel<<<A_BLKS + B_BLKS, 256>>>(z, cb);
    vq_gemm<<<NWORK, 256, SMEM_B>>>();
    fixup_kernel<<<NTOK / 8, 256>>>(cb);
    gather_sph_kernel<<<GT_BLKS + SPH_BLKS, 256, GT_SMEM>>>(cb, ie, pr, out);
}

// round 16
// speedup vs baseline: 1.0516x; 1.0022x over previous
#include <cuda_runtime.h>
#include <cuda_fp16.h>
#include <cstdint>
#include <math.h>

typedef unsigned long long ull;

// ---------------- problem dims ----------------
#define NE     16384
#define CD     256
#define HW     1024
#define NTOK   4096
#define ZQ_N   (NTOK * CD)
#define NCUTS  32
#define EMB    512
#define BATCH  4

// ---------------- GEMM tiling ----------------
#define APLANE  65536
#define BTILE   16384
#define SMEM_B  (APLANE + 3 * BTILE)   // 114688
#define NTILES  2048                   // 32 mtiles x 64 ngrps
#define NWORK   296

// ---------------- device globals ----------------
__device__ __align__(16) __half g_Ah[NTOK * CD];
__device__ __align__(16) __half g_Bh[NE * CD];
__device__ __align__(16) float g_zt[NTOK * CD];
__device__ float g_hn[NE];
__device__ ull   g_top[(size_t)NTOK * 256];
__device__ int   g_best[NTOK];

// ---------------- asm helpers ----------------
static __device__ __forceinline__ uint32_t smem_u32(const void* p) {
    uint32_t a;
    asm("{ .reg .u64 t; cvta.to.shared.u64 t, %1; cvt.u32.u64 %0, t; }" : "=r"(a) : "l"(p));
    return a;
}
static __device__ __forceinline__ void cp16(uint32_t dst, const void* src) {
    asm volatile("cp.async.cg.shared.global [%0], [%1], 16;" :: "r"(dst), "l"(src));
}
static __device__ __forceinline__ void cp_commit() {
    asm volatile("cp.async.commit_group;");
}
template <int N> static __device__ __forceinline__ void cp_wait() {
    asm volatile("cp.async.wait_group %0;" :: "n"(N));
}
#define LDSM4(r, addr) \
    asm volatile("ldmatrix.sync.aligned.m8n8.x4.shared.b16 {%0,%1,%2,%3}, [%4];" \
        : "=r"((r)[0]), "=r"((r)[1]), "=r"((r)[2]), "=r"((r)[3]) : "r"(addr))
#define MMAF16(d, a, b0, b1) \
    asm volatile("mma.sync.aligned.m16n8k16.row.col.f16.f16.f16.f16 " \
        "{%0,%1},{%2,%3,%4,%5},{%6,%7},{%0,%1};" \
        : "+r"((d)[0]), "+r"((d)[1]) \
        : "r"((a)[0]), "r"((a)[1]), "r"((a)[2]), "r"((a)[3]), "r"(b0), "r"(b1))

static __device__ __forceinline__ uint32_t mono_f32(float f) {
    uint32_t b = __float_as_uint(f);
    return b ^ ((uint32_t)(((int)b) >> 31) | 0x80000000u);
}
static __device__ __forceinline__ ull umax64(ull a, ull b) { return a > b ? a : b; }
static __device__ __forceinline__ ull pack_key(float s, int n) {
    return ((ull)mono_f32(s) << 32) | (ull)(NE - 1 - n);
}

// ================= prep: fused z/codebook -> f16 (+ fp32 zt, half-norms) =================
#define A_BLKS (NTOK * 32 / 8 / 32)    // 512
#define B_BLKS ((NE * 32) / 256)       // 2048
__global__ void convAB_kernel(const float* __restrict__ z, const float* __restrict__ cb) {
    if (blockIdx.x < A_BLKS) {
        const int gw = blockIdx.x * 8 + (threadIdx.x >> 5);
        const int lane = threadIdx.x & 31;
        const int tg = gw >> 5, c8 = gw & 31;
        const int token = tg * 32 + lane;
        const int bb = token >> 10, p = token & 1023;
        __align__(16) __half h[8];
        __align__(16) float v[8];
        #pragma unroll
        for (int i = 0; i < 8; i++) {
            v[i] = z[((size_t)bb * CD + c8 * 8 + i) * HW + p];
            h[i] = __float2half(v[i]);
        }
        *(uint4*)&g_Ah[(size_t)token * CD + c8 * 8] = *(const uint4*)h;
        *(float4*)&g_zt[(size_t)token * CD + c8 * 8]     = *(const float4*)v;
        *(float4*)&g_zt[(size_t)token * CD + c8 * 8 + 4] = *(const float4*)(v + 4);
        return;
    }
    int t = (blockIdx.x - A_BLKS) * 256 + threadIdx.x;
    int n = t >> 5, c8 = t & 31;
    __align__(16) __half h[8];
    const float4 v0 = *(const float4*)(cb + (size_t)n * CD + c8 * 8);
    const float4 v1 = *(const float4*)(cb + (size_t)n * CD + c8 * 8 + 4);
    float s = 0.f;
    {
        const float vv[8] = {v0.x, v0.y, v0.z, v0.w, v1.x, v1.y, v1.z, v1.w};
        #pragma unroll
        for (int i = 0; i < 8; i++) {
            h[i] = __float2half(vv[i]);
            s = fmaf(vv[i], vv[i], s);
        }
    }
    *(uint4*)&g_Bh[(size_t)n * CD + c8 * 8] = *(const uint4*)h;
    #pragma unroll
    for (int o = 16; o; o >>= 1) s += __shfl_xor_sync(0xffffffffu, s, o);
    if ((t & 31) == 0) g_hn[n] = 0.5f * s;
}

// ================= persistent tensor-core VQ GEMM (nomination pass) =================
__global__ void __launch_bounds__(256, 2) vq_gemm() {
    extern __shared__ unsigned char smem[];
    const uint32_t sb = smem_u32(smem);
    const int tid = threadIdx.x;
    const int lane = tid & 31;
    const int wid = tid >> 5;
    const int wm = wid >> 1, wn = wid & 1;

    const int w = blockIdx.x;
    const int t0 = (w * NTILES) / NWORK;
    const int t1 = ((w + 1) * NTILES) / NWORK;

    const int arow = tid >> 1, ahalf = tid & 1;
    const int brow = tid >> 1, bhalf = tid & 1;
    const uint32_t a_sm_row = sb + arow * 512;
    const int ar7l = arow & 7;
    const int br7l = brow & 7;

    const int chi = lane >> 4;
    uint32_t a_row_sm[2]; int ar7[2];
    #pragma unroll
    for (int mi = 0; mi < 2; mi++) {
        const int rowA = wm * 32 + mi * 16 + (lane & 15);
        a_row_sm[mi] = sb + rowA * 512;
        ar7[mi] = rowA & 7;
    }
    uint32_t b_row_off[4]; int br7[4];
    #pragma unroll
    for (int nf = 0; nf < 4; nf++) {
        const int rowB = wn * 64 + nf * 16 + (lane & 15);
        b_row_off[nf] = rowB * 128;
        br7[nf] = rowB & 7;
    }
    const int cc = (lane & 3) * 2;

    uint32_t acc[2][8][2];
    #pragma unroll
    for (int mi = 0; mi < 2; mi++)
        #pragma unroll
        for (int ni = 0; ni < 8; ni++) { acc[mi][ni][0] = 0u; acc[mi][ni][1] = 0u; }

    float s1[2][2], s2[2][2];
    int   i1[2][2], i2[2][2];
    #pragma unroll
    for (int mi = 0; mi < 2; mi++)
        #pragma unroll
        for (int h = 0; h < 2; h++) {
            s1[mi][h] = -INFINITY; s2[mi][h] = -INFINITY;
            i1[mi][h] = 0;         i2[mi][h] = 0;
        }

    int T = t0;
    while (T < t1) {
        const int mtile = T >> 6;
        const int segEnd = min(t1, (mtile + 1) << 6);
        const int nsl = (segEnd - T) * 8;

        {
            const char* Abase = (const char*)(g_Ah + (size_t)mtile * 128 * CD);
            const char* asrc = Abase + (size_t)arow * 512 + ahalf * 256;
            #pragma unroll
            for (int j = 0; j < 16; j++) {
                const int c16 = ahalf * 16 + j;
                const uint32_t dst = a_sm_row + (c16 >> 3) * 128 + (((c16 & 7) ^ ar7l) << 4);
                cp16(dst, asrc + j * 16);
            }
            #pragma unroll
            for (int s = 0; s < 2; s++) {
                const int ngrp2 = T & 63;
                const int nt = s >> 2, ks = s & 3;
                const char* bsrc = (const char*)g_Bh
                    + (size_t)(ngrp2 * 256 + nt * 128 + brow) * 512 + ks * 128 + bhalf * 64;
                const uint32_t bdst = sb + APLANE + s * BTILE + brow * 128;
                #pragma unroll
                for (int j = 0; j < 4; j++) {
                    const int c16 = bhalf * 4 + j;
                    cp16(bdst + ((c16 ^ br7l) << 4), bsrc + j * 16);
                }
                cp_commit();
            }
        }

        int stage = 0;
        for (int si = 0; si < nsl; si++) {
            const int tile = T + (si >> 3);
            const int s = si & 7, nt = (s >> 2) & 1, ks = s & 3;

            cp_wait<1>();
            __syncthreads();

            const int nsi = si + 2;
            if (nsi < nsl) {
                int pst = stage + 2; if (pst >= 3) pst -= 3;
                const int ntile2 = T + (nsi >> 3);
                const int s2v = nsi & 7, nnt = (s2v >> 2) & 1, nks = s2v & 3;
                const int ngrp2 = ntile2 & 63;
                const char* bsrc = (const char*)g_Bh
                    + (size_t)(ngrp2 * 256 + nnt * 128 + brow) * 512 + nks * 128 + bhalf * 64;
                const uint32_t bdst = sb + APLANE + pst * BTILE + brow * 128;
                #pragma unroll
                for (int j = 0; j < 4; j++) {
                    const int c16 = bhalf * 4 + j;
                    cp16(bdst + ((c16 ^ br7l) << 4), bsrc + j * 16);
                }
            }
            cp_commit();

            const uint32_t sbB = sb + APLANE + stage * BTILE;
            #pragma unroll
            for (int kk = 0; kk < 4; kk++) {
                uint32_t a[2][4], b[4][4];
                const int c16a = kk * 2 + chi;
                #pragma unroll
                for (int mi = 0; mi < 2; mi++)
                    LDSM4(a[mi], a_row_sm[mi] + ks * 128 + ((c16a ^ ar7[mi]) << 4));
                #pragma unroll
                for (int nf = 0; nf < 4; nf++)
                    LDSM4(b[nf], sbB + b_row_off[nf] + ((c16a ^ br7[nf]) << 4));
                #pragma unroll
                for (int mi = 0; mi < 2; mi++)
                    #pragma unroll
                    for (int nf = 0; nf < 4; nf++) {
                        MMAF16(acc[mi][nf * 2 + 0], a[mi], b[nf][0], b[nf][2]);
                        MMAF16(acc[mi][nf * 2 + 1], a[mi], b[nf][1], b[nf][3]);
                    }
            }
            if (++stage == 3) stage = 0;

            if (ks == 3) {
                const int nbase = (tile & 63) * 256 + nt * 128 + wn * 64;
                #pragma unroll
                for (int ni = 0; ni < 8; ni++) {
                    const int n0 = nbase + ni * 8 + cc;
                    const float hn0 = __ldg(&g_hn[n0]);
                    const float hn1 = __ldg(&g_hn[n0 + 1]);
                    #pragma unroll
                    for (int mi = 0; mi < 2; mi++)
                        #pragma unroll
                        for (int h = 0; h < 2; h++) {
                            const float2 f = __half22float2(*(__half2*)&acc[mi][ni][h]);
                            const float sc0 = f.x - hn0;
                            const float sc1 = f.y - hn1;
                            if (sc0 > s1[mi][h]) {
                                s2[mi][h] = s1[mi][h]; i2[mi][h] = i1[mi][h];
                                s1[mi][h] = sc0;       i1[mi][h] = n0;
                            } else if (sc0 > s2[mi][h]) {
                                s2[mi][h] = sc0; i2[mi][h] = n0;
                            }
                            if (sc1 > s1[mi][h]) {
                                s2[mi][h] = s1[mi][h]; i2[mi][h] = i1[mi][h];
                                s1[mi][h] = sc1;       i1[mi][h] = n0 + 1;
                            } else if (sc1 > s2[mi][h]) {
                                s2[mi][h] = sc1; i2[mi][h] = n0 + 1;
                            }
                            acc[mi][ni][h] = 0u;
                        }
                }
            }

            if (s == 7) {
                #pragma unroll
                for (int mi = 0; mi < 2; mi++)
                    #pragma unroll
                    for (int h = 0; h < 2; h++) {
                        float a1 = s1[mi][h], a2 = s2[mi][h];
                        int   x1 = i1[mi][h], x2 = i2[mi][h];
                        #pragma unroll
                        for (int off = 1; off <= 2; off <<= 1) {
                            float b1 = __shfl_xor_sync(0xffffffffu, a1, off);
                            float b2 = __shfl_xor_sync(0xffffffffu, a2, off);
                            int   y1 = __shfl_xor_sync(0xffffffffu, x1, off);
                            int   y2 = __shfl_xor_sync(0xffffffffu, x2, off);
                            if (b1 > a1 || (b1 == a1 && y1 < x1)) {
                                float t = a1; a1 = b1; b1 = t;
                                int  ti = x1; x1 = y1; y1 = ti;
                                t = a2; a2 = b2; b2 = t;
                                ti = x2; x2 = y2; y2 = ti;
                            }
                            if (b1 > a2 || (b1 == a2 && y1 < x2)) { a2 = b1; x2 = y1; }
                        }
                        if ((lane & 3) == 0) {
                            const int token = mtile * 128 + wm * 32 + mi * 16 + h * 8 + (lane >> 2);
                            ull* dst = g_top + (size_t)token * 256 + (tile & 63) * 4 + wn * 2;
                            dst[0] = pack_key(a1, x1);
                            dst[1] = pack_key(a2, x2);
                        }
                        s1[mi][h] = -INFINITY; s2[mi][h] = -INFINITY;
                        i1[mi][h] = 0;         i2[mi][h] = 0;
                    }
            }
        }

        cp_wait<0>();
        __syncthreads();
        T = segEnd;
    }
}

// ================= fixup (+ spherical distance, overlapped) =================
#define FIX_BLKS (NTOK / 8)         // 512
#define SPH_BLKS ((EMB * 8) / 256)  // 16
__global__ void fixup_sph_kernel(const float* __restrict__ cb, const float* __restrict__ ie,
                                 const float* __restrict__ pr, float* __restrict__ out) {
    if (blockIdx.x < FIX_BLKS) {
        const int token = blockIdx.x * 8 + (threadIdx.x >> 5);
        const int lane = threadIdx.x & 31;

        const ull* tp = g_top + (size_t)token * 256;
        ull k[8];
        #pragma unroll
        for (int i = 0; i < 8; i++) k[i] = tp[lane + 32 * i];

        int cand[4];
        #pragma unroll
        for (int r = 0; r < 4; r++) {
            ull m = 0;
            #pragma unroll
            for (int i = 0; i < 8; i++) m = umax64(m, k[i]);
            #pragma unroll
            for (int off = 16; off; off >>= 1)
                m = umax64(m, __shfl_xor_sync(0xffffffffu, m, off));
            #pragma unroll
            for (int i = 0; i < 8; i++) if (k[i] == m) k[i] = 0;
            cand[r] = (NE - 1) - (int)(m & 0xFFFFFFFFull);
        }

        float zv[8];
        #pragma unroll
        for (int i = 0; i < 8; i++)
            zv[i] = g_zt[(size_t)token * CD + lane + 32 * i];

        ull bestk = 0;
        #pragma unroll
        for (int r = 0; r < 4; r++) {
            const int n = cand[r];
            const float* crow = cb + (size_t)n * CD;
            float s = 0.f;
            #pragma unroll
            for (int i = 0; i < 8; i++) s = fmaf(zv[i], __ldg(&crow[lane + 32 * i]), s);
            #pragma unroll
            for (int off = 16; off; off >>= 1) s += __shfl_xor_sync(0xffffffffu, s, off);
            s -= g_hn[n];
            bestk = umax64(bestk, pack_key(s, n));
        }
        if (lane == 0) g_best[token] = (NE - 1) - (int)(bestk & 0xFFFFFFFFull);
        return;
    }
    // ---- spherical distance: 4096 threads = 512 e x 8 cut-groups of 4 ----
    const int idx = (blockIdx.x - FIX_BLKS) * 256 + threadIdx.x;
    const int e = idx >> 3, jg = idx & 7;
    float pv[BATCH];
    float pn = 0.f;
    #pragma unroll
    for (int b = 0; b < BATCH; b++) { pv[b] = pr[b * EMB + e]; pn += pv[b] * pv[b]; }
    pn = fmaxf(sqrtf(pn), 1e-12f);
    #pragma unroll
    for (int b = 0; b < BATCH; b++) pv[b] /= pn;
    float acc = 0.f;
    #pragma unroll
    for (int jj = 0; jj < 4; jj++) {
        const int j = jg * 4 + jj;
        float q[BATCH];
        float qn = 0.f;
        #pragma unroll
        for (int b = 0; b < BATCH; b++) {
            q[b] = ie[(size_t)(j * BATCH + b) * EMB + e];
            qn += q[b] * q[b];
        }
        qn = fmaxf(sqrtf(qn), 1e-12f);
        float d2 = 0.f;
        #pragma unroll
        for (int b = 0; b < BATCH; b++) {
            float df = q[b] / qn - pv[b];
            d2 += df * df;
        }
        float h = fminf(0.5f * sqrtf(d2), 1.0f);
        float a = asinf(h);
        acc += 2.0f * a * a;
    }
    #pragma unroll
    for (int off = 1; off <= 4; off <<= 1)
        acc += __shfl_xor_sync(0xffffffffu, acc, off);
    if (jg == 0) out[ZQ_N + e] = acc * (1.0f / NCUTS);
}

// ================= gather z_q: 256 blocks of 32 tokens x 128 channels =================
#define GT_BLKS (2 * NTOK / 32)     // 256
__global__ void gather_kernel(const float* __restrict__ cb, float* __restrict__ out) {
    extern __shared__ float ts[];       // [32 tokens][129]
    const int tid = threadIdx.x;
    const int grp = blockIdx.x >> 1;    // 32-token group
    const int half = blockIdx.x & 1;    // channel half (0:0-127, 1:128-255)
    const int t0 = grp * 32;

    // phase 1: coalesced codebook half-row loads -> staged transpose
    const int r = tid >> 3, part = tid & 7;   // 32 rows x 8 threads
    const int n = g_best[t0 + r];
    const float* crow = cb + (size_t)n * CD + half * 128;
    float* dst = ts + r * 129;
    #pragma unroll
    for (int j = 0; j < 4; j++) {
        const int cl = part * 4 + j * 32;      // local channel 0..127
        float4 v = *(const float4*)(crow + cl);
        dst[cl + 0] = v.x; dst[cl + 1] = v.y; dst[cl + 2] = v.z; dst[cl + 3] = v.w;
    }
    __syncthreads();

    // phase 2: coalesced stores to [B,C,H,W]
    const int w = tid >> 5, l = tid & 31;
    const int bb = t0 >> 10, p0 = t0 & 1023;
    float* ob = out + (size_t)bb * CD * HW + p0;
    #pragma unroll
    for (int i = 0; i < 16; i++) {
        const int cl = w + 8 * i;              // local channel
        ob[(size_t)(half * 128 + cl) * HW + l] = ts[l * 129 + cl];
    }
}

#define GT_SMEM (32 * 129 * 4)

// ================= launch =================
extern "C" void kernel_launch(void* const* d_in, const int* in_sizes, int n_in,
                              void* d_out, int out_size) {
    const float* z  = (const float*)d_in[0];
    const float* cb = (const float*)d_in[1];
    const float* ie = (const float*)d_in[2];
    const float* pr = (const float*)d_in[3];
    float* out = (float*)d_out;

    cudaFuncSetAttribute(vq_gemm, cudaFuncAttributeMaxDynamicSharedMemorySize, SMEM_B);
    cudaFuncSetAttribute(gather_kernel, cudaFuncAttributeMaxDynamicSharedMemorySize, GT_SMEM);

    convAB_kernel<<<A_BLKS + B_BLKS, 256>>>(z, cb);
    vq_gemm<<<NWORK, 256, SMEM_B>>>();
    fixup_sph_kernel<<<FIX_BLKS + SPH_BLKS, 256>>>(cb, ie, pr, out);
    gather_kernel<<<GT_BLKS, 256, GT_SMEM>>>(cb, out);
}

// round 17
// speedup vs baseline: 1.0793x; 1.0263x over previous
#include <cuda_runtime.h>
#include <cuda_fp16.h>
#include <cstdint>
#include <math.h>

typedef unsigned long long ull;

// ---------------- problem dims ----------------
#define NE     16384
#define CD     256
#define HW     1024
#define NTOK   4096
#define ZQ_N   (NTOK * CD)
#define NCUTS  32
#define EMB    512
#define BATCH  4

// ---------------- GEMM tiling ----------------
#define APLANE  65536
#define BTILE   16384
#define SMEM_B  (APLANE + 3 * BTILE)   // 114688
#define NTILES  2048                   // 32 mtiles x 64 ngrps
#define NWORK   296

// ---------------- device globals ----------------
__device__ __align__(16) __half g_Ah[NTOK * CD];
__device__ __align__(16) __half g_Bh[NE * CD];
__device__ __align__(16) float g_zt[NTOK * CD];
__device__ float g_hn[NE];
__device__ __align__(16) uint32_t g_top[(size_t)NTOK * 256];  // 32-bit keys: 18b score | 14b (NE-1-n)
__device__ int   g_best[NTOK];

// ---------------- asm helpers ----------------
static __device__ __forceinline__ uint32_t smem_u32(const void* p) {
    uint32_t a;
    asm("{ .reg .u64 t; cvta.to.shared.u64 t, %1; cvt.u32.u64 %0, t; }" : "=r"(a) : "l"(p));
    return a;
}
static __device__ __forceinline__ void cp16(uint32_t dst, const void* src) {
    asm volatile("cp.async.cg.shared.global [%0], [%1], 16;" :: "r"(dst), "l"(src));
}
static __device__ __forceinline__ void cp_commit() {
    asm volatile("cp.async.commit_group;");
}
template <int N> static __device__ __forceinline__ void cp_wait() {
    asm volatile("cp.async.wait_group %0;" :: "n"(N));
}
#define LDSM4(r, addr) \
    asm volatile("ldmatrix.sync.aligned.m8n8.x4.shared.b16 {%0,%1,%2,%3}, [%4];" \
        : "=r"((r)[0]), "=r"((r)[1]), "=r"((r)[2]), "=r"((r)[3]) : "r"(addr))
#define MMAF16(d, a, b0, b1) \
    asm volatile("mma.sync.aligned.m16n8k16.row.col.f16.f16.f16.f16 " \
        "{%0,%1},{%2,%3,%4,%5},{%6,%7},{%0,%1};" \
        : "+r"((d)[0]), "+r"((d)[1]) \
        : "r"((a)[0]), "r"((a)[1]), "r"((a)[2]), "r"((a)[3]), "r"(b0), "r"(b1))

static __device__ __forceinline__ uint32_t mono_f32(float f) {
    uint32_t b = __float_as_uint(f);
    return b ^ ((uint32_t)(((int)b) >> 31) | 0x80000000u);
}
static __device__ __forceinline__ ull umax64(ull a, ull b) { return a > b ? a : b; }
static __device__ __forceinline__ ull pack_key(float s, int n) {
    return ((ull)mono_f32(s) << 32) | (ull)(NE - 1 - n);
}
// 32-bit candidate key: top 18 bits of monotone score | 14-bit reversed index
static __device__ __forceinline__ uint32_t pack_key32(float s, int n) {
    return (mono_f32(s) & 0xFFFFC000u) | (uint32_t)(NE - 1 - n);
}

// ================= prep: fused z/codebook -> f16 (+ fp32 zt, half-norms) =================
#define A_BLKS (NTOK * 32 / 8 / 32)    // 512
#define B_BLKS ((NE * 32) / 256)       // 2048
__global__ void convAB_kernel(const float* __restrict__ z, const float* __restrict__ cb) {
    if (blockIdx.x < A_BLKS) {
        const int gw = blockIdx.x * 8 + (threadIdx.x >> 5);
        const int lane = threadIdx.x & 31;
        const int tg = gw >> 5, c8 = gw & 31;
        const int token = tg * 32 + lane;
        const int bb = token >> 10, p = token & 1023;
        __align__(16) __half h[8];
        __align__(16) float v[8];
        #pragma unroll
        for (int i = 0; i < 8; i++) {
            v[i] = z[((size_t)bb * CD + c8 * 8 + i) * HW + p];
            h[i] = __float2half(v[i]);
        }
        *(uint4*)&g_Ah[(size_t)token * CD + c8 * 8] = *(const uint4*)h;
        *(float4*)&g_zt[(size_t)token * CD + c8 * 8]     = *(const float4*)v;
        *(float4*)&g_zt[(size_t)token * CD + c8 * 8 + 4] = *(const float4*)(v + 4);
        return;
    }
    int t = (blockIdx.x - A_BLKS) * 256 + threadIdx.x;
    int n = t >> 5, c8 = t & 31;
    __align__(16) __half h[8];
    const float4 v0 = *(const float4*)(cb + (size_t)n * CD + c8 * 8);
    const float4 v1 = *(const float4*)(cb + (size_t)n * CD + c8 * 8 + 4);
    float s = 0.f;
    {
        const float vv[8] = {v0.x, v0.y, v0.z, v0.w, v1.x, v1.y, v1.z, v1.w};
        #pragma unroll
        for (int i = 0; i < 8; i++) {
            h[i] = __float2half(vv[i]);
            s = fmaf(vv[i], vv[i], s);
        }
    }
    *(uint4*)&g_Bh[(size_t)n * CD + c8 * 8] = *(const uint4*)h;
    #pragma unroll
    for (int o = 16; o; o >>= 1) s += __shfl_xor_sync(0xffffffffu, s, o);
    if ((t & 31) == 0) g_hn[n] = 0.5f * s;
}

// ================= persistent tensor-core VQ GEMM (nomination pass) =================
__global__ void __launch_bounds__(256, 2) vq_gemm() {
    extern __shared__ unsigned char smem[];
    const uint32_t sb = smem_u32(smem);
    const int tid = threadIdx.x;
    const int lane = tid & 31;
    const int wid = tid >> 5;
    const int wm = wid >> 1, wn = wid & 1;

    const int w = blockIdx.x;
    const int t0 = (w * NTILES) / NWORK;
    const int t1 = ((w + 1) * NTILES) / NWORK;

    const int arow = tid >> 1, ahalf = tid & 1;
    const int brow = tid >> 1, bhalf = tid & 1;
    const uint32_t a_sm_row = sb + arow * 512;
    const int ar7l = arow & 7;
    const int br7l = brow & 7;

    const int chi = lane >> 4;
    uint32_t a_row_sm[2]; int ar7[2];
    #pragma unroll
    for (int mi = 0; mi < 2; mi++) {
        const int rowA = wm * 32 + mi * 16 + (lane & 15);
        a_row_sm[mi] = sb + rowA * 512;
        ar7[mi] = rowA & 7;
    }
    uint32_t b_row_off[4]; int br7[4];
    #pragma unroll
    for (int nf = 0; nf < 4; nf++) {
        const int rowB = wn * 64 + nf * 16 + (lane & 15);
        b_row_off[nf] = rowB * 128;
        br7[nf] = rowB & 7;
    }
    const int cc = (lane & 3) * 2;

    uint32_t acc[2][8][2];
    #pragma unroll
    for (int mi = 0; mi < 2; mi++)
        #pragma unroll
        for (int ni = 0; ni < 8; ni++) { acc[mi][ni][0] = 0u; acc[mi][ni][1] = 0u; }

    float s1[2][2], s2[2][2];
    int   i1[2][2], i2[2][2];
    #pragma unroll
    for (int mi = 0; mi < 2; mi++)
        #pragma unroll
        for (int h = 0; h < 2; h++) {
            s1[mi][h] = -INFINITY; s2[mi][h] = -INFINITY;
            i1[mi][h] = 0;         i2[mi][h] = 0;
        }

    int T = t0;
    while (T < t1) {
        const int mtile = T >> 6;
        const int segEnd = min(t1, (mtile + 1) << 6);
        const int nsl = (segEnd - T) * 8;

        {
            const char* Abase = (const char*)(g_Ah + (size_t)mtile * 128 * CD);
            const char* asrc = Abase + (size_t)arow * 512 + ahalf * 256;
            #pragma unroll
            for (int j = 0; j < 16; j++) {
                const int c16 = ahalf * 16 + j;
                const uint32_t dst = a_sm_row + (c16 >> 3) * 128 + (((c16 & 7) ^ ar7l) << 4);
                cp16(dst, asrc + j * 16);
            }
            #pragma unroll
            for (int s = 0; s < 2; s++) {
                const int ngrp2 = T & 63;
                const int nt = s >> 2, ks = s & 3;
                const char* bsrc = (const char*)g_Bh
                    + (size_t)(ngrp2 * 256 + nt * 128 + brow) * 512 + ks * 128 + bhalf * 64;
                const uint32_t bdst = sb + APLANE + s * BTILE + brow * 128;
                #pragma unroll
                for (int j = 0; j < 4; j++) {
                    const int c16 = bhalf * 4 + j;
                    cp16(bdst + ((c16 ^ br7l) << 4), bsrc + j * 16);
                }
                cp_commit();
            }
        }

        int stage = 0;
        for (int si = 0; si < nsl; si++) {
            const int tile = T + (si >> 3);
            const int s = si & 7, nt = (s >> 2) & 1, ks = s & 3;

            cp_wait<1>();
            __syncthreads();

            const int nsi = si + 2;
            if (nsi < nsl) {
                int pst = stage + 2; if (pst >= 3) pst -= 3;
                const int ntile2 = T + (nsi >> 3);
                const int s2v = nsi & 7, nnt = (s2v >> 2) & 1, nks = s2v & 3;
                const int ngrp2 = ntile2 & 63;
                const char* bsrc = (const char*)g_Bh
                    + (size_t)(ngrp2 * 256 + nnt * 128 + brow) * 512 + nks * 128 + bhalf * 64;
                const uint32_t bdst = sb + APLANE + pst * BTILE + brow * 128;
                #pragma unroll
                for (int j = 0; j < 4; j++) {
                    const int c16 = bhalf * 4 + j;
                    cp16(bdst + ((c16 ^ br7l) << 4), bsrc + j * 16);
                }
            }
            cp_commit();

            const uint32_t sbB = sb + APLANE + stage * BTILE;
            #pragma unroll
            for (int kk = 0; kk < 4; kk++) {
                uint32_t a[2][4], b[4][4];
                const int c16a = kk * 2 + chi;
                #pragma unroll
                for (int mi = 0; mi < 2; mi++)
                    LDSM4(a[mi], a_row_sm[mi] + ks * 128 + ((c16a ^ ar7[mi]) << 4));
                #pragma unroll
                for (int nf = 0; nf < 4; nf++)
                    LDSM4(b[nf], sbB + b_row_off[nf] + ((c16a ^ br7[nf]) << 4));
                #pragma unroll
                for (int mi = 0; mi < 2; mi++)
                    #pragma unroll
                    for (int nf = 0; nf < 4; nf++) {
                        MMAF16(acc[mi][nf * 2 + 0], a[mi], b[nf][0], b[nf][2]);
                        MMAF16(acc[mi][nf * 2 + 1], a[mi], b[nf][1], b[nf][3]);
                    }
            }
            if (++stage == 3) stage = 0;

            if (ks == 3) {
                const int nbase = (tile & 63) * 256 + nt * 128 + wn * 64;
                #pragma unroll
                for (int ni = 0; ni < 8; ni++) {
                    const int n0 = nbase + ni * 8 + cc;
                    const float hn0 = __ldg(&g_hn[n0]);
                    const float hn1 = __ldg(&g_hn[n0 + 1]);
                    #pragma unroll
                    for (int mi = 0; mi < 2; mi++)
                        #pragma unroll
                        for (int h = 0; h < 2; h++) {
                            const float2 f = __half22float2(*(__half2*)&acc[mi][ni][h]);
                            const float sc0 = f.x - hn0;
                            const float sc1 = f.y - hn1;
                            if (sc0 > s1[mi][h]) {
                                s2[mi][h] = s1[mi][h]; i2[mi][h] = i1[mi][h];
                                s1[mi][h] = sc0;       i1[mi][h] = n0;
                            } else if (sc0 > s2[mi][h]) {
                                s2[mi][h] = sc0; i2[mi][h] = n0;
                            }
                            if (sc1 > s1[mi][h]) {
                                s2[mi][h] = s1[mi][h]; i2[mi][h] = i1[mi][h];
                                s1[mi][h] = sc1;       i1[mi][h] = n0 + 1;
                            } else if (sc1 > s2[mi][h]) {
                                s2[mi][h] = sc1; i2[mi][h] = n0 + 1;
                            }
                            acc[mi][ni][h] = 0u;
                        }
                }
            }

            if (s == 7) {
                #pragma unroll
                for (int mi = 0; mi < 2; mi++)
                    #pragma unroll
                    for (int h = 0; h < 2; h++) {
                        float a1 = s1[mi][h], a2 = s2[mi][h];
                        int   x1 = i1[mi][h], x2 = i2[mi][h];
                        #pragma unroll
                        for (int off = 1; off <= 2; off <<= 1) {
                            float b1 = __shfl_xor_sync(0xffffffffu, a1, off);
                            float b2 = __shfl_xor_sync(0xffffffffu, a2, off);
                            int   y1 = __shfl_xor_sync(0xffffffffu, x1, off);
                            int   y2 = __shfl_xor_sync(0xffffffffu, x2, off);
                            if (b1 > a1 || (b1 == a1 && y1 < x1)) {
                                float t = a1; a1 = b1; b1 = t;
                                int  ti = x1; x1 = y1; y1 = ti;
                                t = a2; a2 = b2; b2 = t;
                                ti = x2; x2 = y2; y2 = ti;
                            }
                            if (b1 > a2 || (b1 == a2 && y1 < x2)) { a2 = b1; x2 = y1; }
                        }
                        if ((lane & 3) == 0) {
                            const int token = mtile * 128 + wm * 32 + mi * 16 + h * 8 + (lane >> 2);
                            uint32_t* dst = g_top + (size_t)token * 256 + (tile & 63) * 4 + wn * 2;
                            dst[0] = pack_key32(a1, x1);
                            dst[1] = pack_key32(a2, x2);
                        }
                        s1[mi][h] = -INFINITY; s2[mi][h] = -INFINITY;
                        i1[mi][h] = 0;         i2[mi][h] = 0;
                    }
            }
        }

        cp_wait<0>();
        __syncthreads();
        T = segEnd;
    }
}

// ================= fixup (+ spherical distance, overlapped) =================
#define FIX_BLKS (NTOK / 8)         // 512
#define SPH_BLKS ((EMB * 8) / 256)  // 16
__global__ void fixup_sph_kernel(const float* __restrict__ cb, const float* __restrict__ ie,
                                 const float* __restrict__ pr, float* __restrict__ out) {
    if (blockIdx.x < FIX_BLKS) {
        const int token = blockIdx.x * 8 + (threadIdx.x >> 5);
        const int lane = threadIdx.x & 31;

        const uint32_t* tp = g_top + (size_t)token * 256;
        uint32_t k[8];
        #pragma unroll
        for (int i = 0; i < 8; i++) k[i] = tp[lane + 32 * i];

        int cand[4];
        #pragma unroll
        for (int r = 0; r < 4; r++) {
            uint32_t m = 0;
            #pragma unroll
            for (int i = 0; i < 8; i++) m = max(m, k[i]);
            #pragma unroll
            for (int off = 16; off; off >>= 1)
                m = max(m, __shfl_xor_sync(0xffffffffu, m, off));
            #pragma unroll
            for (int i = 0; i < 8; i++) if (k[i] == m) k[i] = 0;
            cand[r] = (NE - 1) - (int)(m & 0x3FFFu);
        }

        float zv[8];
        #pragma unroll
        for (int i = 0; i < 8; i++)
            zv[i] = g_zt[(size_t)token * CD + lane + 32 * i];

        ull bestk = 0;
        #pragma unroll
        for (int r = 0; r < 4; r++) {
            const int n = cand[r];
            const float* crow = cb + (size_t)n * CD;
            float s = 0.f;
            #pragma unroll
            for (int i = 0; i < 8; i++) s = fmaf(zv[i], __ldg(&crow[lane + 32 * i]), s);
            #pragma unroll
            for (int off = 16; off; off >>= 1) s += __shfl_xor_sync(0xffffffffu, s, off);
            s -= g_hn[n];
            bestk = umax64(bestk, pack_key(s, n));
        }
        if (lane == 0) g_best[token] = (NE - 1) - (int)(bestk & 0xFFFFFFFFull);
        return;
    }
    // ---- spherical distance: 4096 threads = 512 e x 8 cut-groups of 4 ----
    const int idx = (blockIdx.x - FIX_BLKS) * 256 + threadIdx.x;
    const int e = idx >> 3, jg = idx & 7;
    float pv[BATCH];
    float pn = 0.f;
    #pragma unroll
    for (int b = 0; b < BATCH; b++) { pv[b] = pr[b * EMB + e]; pn += pv[b] * pv[b]; }
    pn = fmaxf(sqrtf(pn), 1e-12f);
    #pragma unroll
    for (int b = 0; b < BATCH; b++) pv[b] /= pn;
    float acc = 0.f;
    #pragma unroll
    for (int jj = 0; jj < 4; jj++) {
        const int j = jg * 4 + jj;
        float q[BATCH];
        float qn = 0.f;
        #pragma unroll
        for (int b = 0; b < BATCH; b++) {
            q[b] = ie[(size_t)(j * BATCH + b) * EMB + e];
            qn += q[b] * q[b];
        }
        qn = fmaxf(sqrtf(qn), 1e-12f);
        float d2 = 0.f;
        #pragma unroll
        for (int b = 0; b < BATCH; b++) {
            float df = q[b] / qn - pv[b];
            d2 += df * df;
        }
        float h = fminf(0.5f * sqrtf(d2), 1.0f);
        float a = asinf(h);
        acc += 2.0f * a * a;
    }
    #pragma unroll
    for (int off = 1; off <= 4; off <<= 1)
        acc += __shfl_xor_sync(0xffffffffu, acc, off);
    if (jg == 0) out[ZQ_N + e] = acc * (1.0f / NCUTS);
}

// ================= gather z_q: 512 blocks of 32 tokens x 64 channels =================
#define GT_BLKS (4 * NTOK / 32)     // 512
__global__ void gather_kernel(const float* __restrict__ cb, float* __restrict__ out) {
    extern __shared__ float ts[];       // [32 tokens][65]
    const int tid = threadIdx.x;
    const int grp = blockIdx.x >> 2;    // 32-token group
    const int quart = blockIdx.x & 3;   // channel quarter
    const int t0 = grp * 32;

    // phase 1: coalesced codebook quarter-row loads -> staged transpose
    const int r = tid >> 3, part = tid & 7;   // 32 rows x 8 threads
    const int n = g_best[t0 + r];
    const float* crow = cb + (size_t)n * CD + quart * 64;
    float* dst = ts + r * 65;
    #pragma unroll
    for (int j = 0; j < 2; j++) {
        const int cl = part * 4 + j * 32;      // local channel 0..63
        float4 v = *(const float4*)(crow + cl);
        dst[cl + 0] = v.x; dst[cl + 1] = v.y; dst[cl + 2] = v.z; dst[cl + 3] = v.w;
    }
    __syncthreads();

    // phase 2: coalesced stores to [B,C,H,W]
    const int w = tid >> 5, l = tid & 31;
    const int bb = t0 >> 10, p0 = t0 & 1023;
    float* ob = out + (size_t)bb * CD * HW + p0;
    #pragma unroll
    for (int i = 0; i < 8; i++) {
        const int cl = w + 8 * i;              // local channel 0..63
        ob[(size_t)(quart * 64 + cl) * HW + l] = ts[l * 65 + cl];
    }
}

#define GT_SMEM (32 * 65 * 4)

// ================= launch =================
extern "C" void kernel_launch(void* const* d_in, const int* in_sizes, int n_in,
                              void* d_out, int out_size) {
    const float* z  = (const float*)d_in[0];
    const float* cb = (const float*)d_in[1];
    const float* ie = (const float*)d_in[2];
    const float* pr = (const float*)d_in[3];
    float* out = (float*)d_out;

    cudaFuncSetAttribute(vq_gemm, cudaFuncAttributeMaxDynamicSharedMemorySize, SMEM_B);
    cudaFuncSetAttribute(gather_kernel, cudaFuncAttributeMaxDynamicSharedMemorySize, GT_SMEM);

    convAB_kernel<<<A_BLKS + B_BLKS, 256>>>(z, cb);
    vq_gemm<<<NWORK, 256, SMEM_B>>>();
    fixup_sph_kernel<<<FIX_BLKS + SPH_BLKS, 256>>>(cb, ie, pr, out);
    gather_kernel<<<GT_BLKS, 256, GT_SMEM>>>(cb, out);
}